// round 17
// baseline (speedup 1.0000x reference)
#include <cuda_runtime.h>
#include <cuda_fp16.h>
#include <cstdint>

#define B_DIM 512
#define F_DIM 784
#define R_DIM 512
#define C_DIM 16
#define D_DIM 49
#define HALF_LOG_2PI 0.9189385332046727f

// Scratch (allocation-free rule: __device__ globals)
__device__ uint32_t g_x2T[F_DIM * B_DIM];       // [f][b] half2(x^2, x) (1.6MB, L2)
__device__ uint32_t g_W[R_DIM * C_DIM * 56];    // [(r*16+c)][56] half2(A,B), d-padded
__device__ float    g_base[R_DIM * C_DIM];      // [r*16+c]

__device__ __forceinline__ uint32_t pack_h2(float lo, float hi) {
    __half2 h = __floats2half2_rn(lo, hi);      // .x(low)=lo, .y(high)=hi
    return *reinterpret_cast<uint32_t*>(&h);
}
__device__ __forceinline__ uint32_t smem_u32(const void* p) {
    uint32_t a;
    asm("{ .reg .u64 t; cvta.to.shared.u64 t, %1; cvt.u32.u64 %0, t; }" : "=r"(a) : "l"(p));
    return a;
}
// one-instruction bulk gather row: global -> smem via TMA engine (sm_90 PTX)
__device__ __forceinline__ void bulk_cp(uint32_t dst, const void* src,
                                        uint32_t bytes, uint32_t mbar) {
    asm volatile(
        "cp.async.bulk.shared::cluster.global.mbarrier::complete_tx::bytes "
        "[%0], [%1], %2, [%3];"
        :: "r"(dst), "l"(src), "r"(bytes), "r"(mbar) : "memory");
}

// ---------------------------------------------------------------------------
// Kernel 1 (merged): blocks 0..399 transpose+pack x -> x2T = half2(x^2, x);
// blocks 400..911 prep W coefficients (half2(A,B)) + base.
// ---------------------------------------------------------------------------
__global__ void __launch_bounds__(256) setup_kernel(const float* __restrict__ x,
                                                    const float* __restrict__ loc,
                                                    const float* __restrict__ scale) {
    __shared__ float tile[32][33];
    __shared__ float scon[784];

    if (blockIdx.x < 400) {
        // ---- transpose + pack ----
        int bx = blockIdx.x % 25;            // f block
        int by = blockIdx.x / 25;            // b block
        int tx = threadIdx.x & 31, ty = threadIdx.x >> 5;
        int fx = bx * 32 + tx;
        #pragma unroll
        for (int k = 0; k < 32; k += 8) {
            int b = by * 32 + ty + k;
            if (fx < F_DIM) tile[ty + k][tx] = x[b * F_DIM + fx];
        }
        __syncthreads();
        int b_out = by * 32 + tx;
        #pragma unroll
        for (int k = 0; k < 32; k += 8) {
            int f = bx * 32 + ty + k;
            if (f < F_DIM) {
                float v = tile[tx][ty + k];
                g_x2T[f * B_DIM + b_out] = pack_h2(v * v, v);
            }
        }
    } else {
        // ---- prep ----
        int r = blockIdx.x - 400;
        int t = threadIdx.x;
        for (int i = t; i < 784; i += 256) {
            int c = i / D_DIM;
            int d = i - c * D_DIM;
            float lc = loc[r * 784 + i];
            float sc = scale[r * 784 + i];
            float A = 0.0f, Bv = 0.0f, contrib = 0.0f;
            if (sc > 0.0f) {
                float inv = 1.0f / sc;
                float w = inv * inv;
                A = -0.5f * w;
                Bv = w * lc;
                contrib = -0.5f * w * lc * lc - __logf(sc) - HALF_LOG_2PI;
            }                                 // else: reference zeroes NaN logp
            g_W[(r * 16 + c) * 56 + d] = pack_h2(A, Bv);
            scon[i] = contrib;
        }
        for (int i = t; i < 16 * 7; i += 256) {
            int c = i / 7, dl = 49 + (i % 7);
            g_W[(r * 16 + c) * 56 + dl] = 0u;
        }
        __syncthreads();
        if (t < 128) {
            int c = t >> 3, l = t & 7;
            float s = 0.0f;
            for (int d = l; d < D_DIM; d += 8) s += scon[c * D_DIM + d];
            s += __shfl_down_sync(0xffffffffu, s, 4, 8);
            s += __shfl_down_sync(0xffffffffu, s, 2, 8);
            s += __shfl_down_sync(0xffffffffu, s, 1, 8);
            if (l == 0) g_base[r * 16 + c] = s;
        }
    }
}

// ---------------------------------------------------------------------------
// Kernel 2: main — HMMA (mma.sync.m16n8k16, fp16 in / fp32 accum).
// Block = (ONE r, 128-b tile), 256 threads = 8 warps, warp owns 16 m-rows.
//   D[m=128, n=16] = A[m, K=112] @ W[n, K]^T.
// Gather = 49 cp.async.bulk row copies (512B each) + 16 W row copies (224B),
// all credited to ONE mbarrier (expect_tx = 28672B) — replaces ~1792 LDGSTS
// (which were pinned at the LSU 1-op/cyc/SM floor) with 65 TMA-engine ops.
// 6 blocks/SM provide cross-block overlap of TMA latency with MMA.
// ---------------------------------------------------------------------------
#define XS_OFF   0        // u32[56][136] = 7616
#define W_OFF    7616     // u32[16][60]  = 960
#define BASE_OFF 8576     // f32[16]
#define MASK_OFF 8592     // s32[49]
#define SMEM_U32 8644
#define SMEM_BYTES (SMEM_U32 * 4)
#define TX_BYTES (49u * 512u + 16u * 224u)    // 28672

__global__ void __launch_bounds__(256, 6) main_kernel(const int* __restrict__ mask,
                                                      float* __restrict__ out) {
    int r   = blockIdx.x;
    int bq0 = blockIdx.y * 128;
    int tid = threadIdx.x;

    extern __shared__ uint32_t dyn[];
    uint32_t* xs2   = dyn + XS_OFF;       // [56][136] half2(x^2, x)
    uint32_t* sW    = dyn + W_OFF;        // [16][60]  half2(A, B)
    float*    sbase = reinterpret_cast<float*>(dyn + BASE_OFF);
    int*      smask = reinterpret_cast<int*>(dyn + MASK_OFF);
    __shared__ __align__(8) unsigned long long s_mbar;

    uint32_t xs_b = smem_u32(xs2);
    uint32_t w_b  = smem_u32(sW);
    uint32_t mb   = smem_u32(&s_mbar);

    if (tid == 0)
        asm volatile("mbarrier.init.shared.b64 [%0], %1;" :: "r"(mb), "r"(1u) : "memory");
    if (tid < 49) smask[tid] = mask[r * 49 + tid];
    if (tid >= 64 && tid < 80) sbase[tid - 64] = g_base[r * 16 + (tid - 64)];
    // zero pad rows d = 49..55 (MMA reads rows <= 55)
    for (int i = tid; i < 224; i += 256) {
        int rr = i >> 5, q = i & 31;
        *reinterpret_cast<uint4*>(xs2 + (49 + rr) * 136 + q * 4)
            = make_uint4(0u, 0u, 0u, 0u);
    }
    __syncthreads();                      // mbar init + smask + pads visible

    // ---- thread 0: credit the barrier, then fire all bulk copies ----
    if (tid == 0) {
        asm volatile("mbarrier.arrive.expect_tx.shared.b64 _, [%0], %1;"
                     :: "r"(mb), "r"(TX_BYTES) : "memory");
        const uint32_t* xsrc = g_x2T + bq0;
        #pragma unroll 7
        for (int d = 0; d < D_DIM; ++d)
            bulk_cp(xs_b + (uint32_t)(d * 136) * 4u,
                    xsrc + (size_t)smask[d] * B_DIM, 512u, mb);
        const uint32_t* gw = g_W + (size_t)r * 16 * 56;
        #pragma unroll
        for (int n = 0; n < 16; ++n)
            bulk_cp(w_b + (uint32_t)(n * 60) * 4u, gw + n * 56, 224u, mb);
    }

    // ---- MMA setup while copies fly ----
    int wid  = tid >> 5;
    int lane = tid & 31;
    int lq = lane >> 2;                   // 0..7
    int lr = lane & 3;                    // 0..3
    int m0 = wid * 16;

    float acc[2][4];                      // [ntile][c0..c3]
    #pragma unroll
    for (int t = 0; t < 2; ++t)
        #pragma unroll
        for (int j = 0; j < 4; ++j) acc[t][j] = 0.0f;

    const uint32_t* xA = xs2 + lr * 136 + m0 + lq;
    const uint32_t* wB = sW + lq * 60 + lr;

    // ---- wait for all 28672 bytes ----
    {
        uint32_t done;
        asm volatile("{\n\t.reg .pred p;\n\t"
                     "mbarrier.try_wait.parity.acquire.cta.shared::cta.b64 p, [%1], %2;\n\t"
                     "selp.b32 %0, 1, 0, p;\n\t}"
                     : "=r"(done) : "r"(mb), "r"(0u) : "memory");
        if (!done) {
            asm volatile("{\n\t.reg .pred P1;\n\t"
                         "WL%=:\n\t"
                         "mbarrier.try_wait.parity.acquire.cta.shared::cta.b64 P1, [%0], %1, 0x989680;\n\t"
                         "@P1 bra.uni WD%=;\n\t"
                         "bra.uni WL%=;\n\t"
                         "WD%=:\n\t}"
                         :: "r"(mb), "r"(0u) : "memory");
        }
    }

    // ---- MMA: all 7 ksteps ----
    #pragma unroll
    for (int ks = 0; ks < 7; ++ks) {
        int xo = (ks * 8) * 136;
        uint32_t a0 = xA[xo];
        uint32_t a1 = xA[xo + 8];
        uint32_t a2 = xA[xo + 4 * 136];
        uint32_t a3 = xA[xo + 4 * 136 + 8];
        #pragma unroll
        for (int t = 0; t < 2; ++t) {
            int wo = t * 8 * 60 + ks * 8;
            uint32_t b0 = wB[wo];
            uint32_t b1 = wB[wo + 4];
            asm volatile(
                "mma.sync.aligned.m16n8k16.row.col.f32.f16.f16.f32 "
                "{%0,%1,%2,%3}, {%4,%5,%6,%7}, {%8,%9}, {%0,%1,%2,%3};"
                : "+f"(acc[t][0]), "+f"(acc[t][1]), "+f"(acc[t][2]), "+f"(acc[t][3])
                : "r"(a0), "r"(a1), "r"(a2), "r"(a3), "r"(b0), "r"(b1));
        }
    }

    // ---- epilogue: add base, store float2 pairs ----
    #pragma unroll
    for (int t = 0; t < 2; ++t) {
        int nc = t * 8 + lr * 2;                    // 0..15
        float bb0 = sbase[nc];
        float bb1 = sbase[nc + 1];
        size_t col = (size_t)r * 16 + nc;
        size_t row0 = (size_t)(bq0 + m0 + lq) * (R_DIM * C_DIM);
        size_t row1 = row0 + 8 * (R_DIM * C_DIM);
        *reinterpret_cast<float2*>(out + row0 + col)
            = make_float2(acc[t][0] + bb0, acc[t][1] + bb1);
        *reinterpret_cast<float2*>(out + row1 + col)
            = make_float2(acc[t][2] + bb0, acc[t][3] + bb1);
    }
}

// ---------------------------------------------------------------------------
extern "C" void kernel_launch(void* const* d_in, const int* in_sizes, int n_in,
                              void* d_out, int out_size) {
    const float* x     = (const float*)d_in[0];
    const int*   mask  = (const int*)d_in[1];
    const float* loc   = (const float*)d_in[2];
    const float* scale = (const float*)d_in[3];
    float* out = (float*)d_out;

    cudaFuncSetAttribute(main_kernel, cudaFuncAttributeMaxDynamicSharedMemorySize,
                         SMEM_BYTES);
    setup_kernel<<<912, 256>>>(x, loc, scale);
    main_kernel<<<dim3(R_DIM, B_DIM / 128), 256, SMEM_BYTES>>>(mask, out);
}